// round 13
// baseline (speedup 1.0000x reference)
#include <cuda_runtime.h>
#include <math.h>

#define NROWS 8192
#define DIM   512
#define NTRIP 200000
#define GRID  1036   // 7 blocks/SM x 148 SMs -> one wave at 36 regs

// Scratch (no allocations allowed in kernel_launch)
__device__ float        g_xn[NROWS];
__device__ float        g_sc[NROWS];                 // per-row dequant scale
__device__ double       g_acc;
__device__ unsigned int g_done;
__device__ int          g_xq[NROWS * DIM / 4];       // 4 MB int8 copy (packed s8x4)
__device__ uint4        g_tp[NTRIP];                 // 3.2 MB packed indices {a,p,n,0}

// ---------------------------------------------------------------------------
// Kernel 1: prep — per-row norm/max + int8 quantize (one warp per row).
// Block 0 thread 0 also resets the accumulators.
// ---------------------------------------------------------------------------
__global__ void prep_kernel(const float* __restrict__ x) {
    if (blockIdx.x == 0 && threadIdx.x == 0) {
        g_acc  = 0.0;
        g_done = 0u;
    }

    int lane = threadIdx.x & 31;
    int row  = (blockIdx.x * blockDim.x + threadIdx.x) >> 5;
    if (row >= NROWS) return;

    const float4* rf = (const float4*)(x + (size_t)row * DIM);

    float4 v[4];
    float s = 0.f, m = 0.f;
#pragma unroll
    for (int k = 0; k < 4; k++) {
        v[k] = __ldg(&rf[lane + 32 * k]);
        s += v[k].x * v[k].x + v[k].y * v[k].y + v[k].z * v[k].z + v[k].w * v[k].w;
        m = fmaxf(m, fmaxf(fmaxf(fabsf(v[k].x), fabsf(v[k].y)),
                           fmaxf(fabsf(v[k].z), fabsf(v[k].w))));
    }
#pragma unroll
    for (int o = 16; o; o >>= 1) {
        s += __shfl_xor_sync(0xFFFFFFFFu, s, o);
        m = fmaxf(m, __shfl_xor_sync(0xFFFFFFFFu, m, o));
    }

    float scale = (m > 0.f) ? (m / 127.f) : 1.f;
    float inv   = (m > 0.f) ? (127.f / m) : 0.f;
    if (lane == 0) { g_xn[row] = s; g_sc[row] = scale; }

    int* qrow = g_xq + (size_t)row * (DIM / 4);
#pragma unroll
    for (int k = 0; k < 4; k++) {
        int qx = __float2int_rn(v[k].x * inv);
        int qy = __float2int_rn(v[k].y * inv);
        int qz = __float2int_rn(v[k].z * inv);
        int qw = __float2int_rn(v[k].w * inv);
        unsigned int packed = (unsigned int)(qx & 0xFF)
                            | ((unsigned int)(qy & 0xFF) << 8)
                            | ((unsigned int)(qz & 0xFF) << 16)
                            | ((unsigned int)(qw & 0xFF) << 24);
        qrow[lane + 32 * k] = (int)packed;   // coalesced STG.32
    }
}

// ---------------------------------------------------------------------------
// Kernel 1b: pack triplets -> uint4{a,p,n,0}. Per-block dtype detect (shared
// flag) so there is no cross-kernel ordering dependence.
// ---------------------------------------------------------------------------
__global__ void pack_kernel(const void* __restrict__ trip_raw) {
    __shared__ int s_is64;
    if (threadIdx.x == 0) {
        const unsigned int* tw = (const unsigned int*)trip_raw;
        int all_zero = 1;
        for (int i = 1; i < 96; i += 2) {
            if (tw[i] != 0u) { all_zero = 0; break; }
        }
        s_is64 = all_zero;
    }
    __syncthreads();

    int t = blockIdx.x * blockDim.x + threadIdx.x;
    if (t >= NTRIP) return;

    unsigned int a, p, n;
    if (s_is64) {
        const long long* t64 = (const long long*)trip_raw;
        a = (unsigned int)__ldg(&t64[3 * t + 0]);
        p = (unsigned int)__ldg(&t64[3 * t + 1]);
        n = (unsigned int)__ldg(&t64[3 * t + 2]);
    } else {
        const int* t32 = (const int*)trip_raw;
        a = (unsigned int)__ldg(&t32[3 * t + 0]);
        p = (unsigned int)__ldg(&t32[3 * t + 1]);
        n = (unsigned int)__ldg(&t32[3 * t + 2]);
    }
    g_tp[t] = make_uint4(a, p, n, 0u);
}

// ---------------------------------------------------------------------------
// Kernel 2: 8-lane-group int8 gather + dp4a dots, 4 triplets/warp/iter.
// 2-deep software pipeline over K-chunks: next chunk's loads in flight while
// current chunk's dp4a runs (6 outstanding LDG.128/warp).
// ---------------------------------------------------------------------------
__global__ void __launch_bounds__(256, 7) trip_kernel(float* __restrict__ out)
{
    const int lane  = threadIdx.x & 31;
    const int grp   = lane >> 3;                  // 0..3: triplet group in warp
    const int sub   = lane & 7;                   // 0..7: lane within group
    const int wib   = threadIdx.x >> 5;
    const int wpb   = blockDim.x >> 5;
    const int gwarp = blockIdx.x * wpb + wib;

    const uint4* xq = (const uint4*)g_xq;         // 32 uint4 per row
    float wsum = 0.f;                             // nonzero only on sub==0 lanes

    const int stride = GRID * 8 * 4;              // warps * triplets/warp

    for (int base = gwarp * 4; base < NTRIP; base += stride) {
        int t = base + grp;
        const int valid = (t < NTRIP);
        int tc = valid ? t : (NTRIP - 1);         // clamp to stay in bounds

        uint4 idx = __ldg(&g_tp[tc]);             // broadcast within group
        const unsigned int a = idx.x, p = idx.y, n = idx.z;

        unsigned int oa = a * 32u + sub;
        unsigned int op = p * 32u + sub;
        unsigned int on = n * 32u + sub;

        // prologue: chunk 0 in flight
        uint4 qa0 = __ldg(&xq[oa]);
        uint4 qp0 = __ldg(&xq[op]);
        uint4 qn0 = __ldg(&xq[on]);

        int iap = 0, ian = 0;
#pragma unroll
        for (int c = 0; c < 4; c++) {
            uint4 qa1, qp1, qn1;
            if (c < 3) {                          // issue next chunk first
                qa1 = __ldg(&xq[oa + 8u * (c + 1)]);
                qp1 = __ldg(&xq[op + 8u * (c + 1)]);
                qn1 = __ldg(&xq[on + 8u * (c + 1)]);
            }
            iap = __dp4a((int)qa0.x, (int)qp0.x, iap);
            ian = __dp4a((int)qa0.x, (int)qn0.x, ian);
            iap = __dp4a((int)qa0.y, (int)qp0.y, iap);
            ian = __dp4a((int)qa0.y, (int)qn0.y, ian);
            iap = __dp4a((int)qa0.z, (int)qp0.z, iap);
            ian = __dp4a((int)qa0.z, (int)qn0.z, ian);
            iap = __dp4a((int)qa0.w, (int)qp0.w, iap);
            ian = __dp4a((int)qa0.w, (int)qn0.w, ian);
            if (c < 3) { qa0 = qa1; qp0 = qp1; qn0 = qn1; }
        }

        // 8-lane butterfly; one instruction serves all 4 groups
#pragma unroll
        for (int o = 4; o; o >>= 1) {
            iap += __shfl_xor_sync(0xFFFFFFFFu, iap, o);
            ian += __shfl_xor_sync(0xFFFFFFFFu, ian, o);
        }

        if (sub == 0 && valid) {
            float sa = g_sc[a];
            float dot_ap = sa * g_sc[p] * (float)iap;
            float dot_an = sa * g_sc[n] * (float)ian;
            float xna = g_xn[a];
            float dap = fmaxf(xna + g_xn[p] - 2.f * dot_ap, 0.f);
            float dan = fmaxf(xna + g_xn[n] - 2.f * dot_an, 0.f);
            float z = dap - dan;
            float sp = (z > 0.f) ? (z + log1pf(expf(-z))) : log1pf(expf(z));
            wsum += sp;
        }
    }

    // Combine the 4 group sums (lanes 0,8,16,24 hold values; others hold 0)
    wsum += __shfl_xor_sync(0xFFFFFFFFu, wsum, 8);
    wsum += __shfl_xor_sync(0xFFFFFFFFu, wsum, 16);

    __shared__ float ssum[8];
    if (lane == 0) ssum[wib] = wsum;
    __syncthreads();
    if (threadIdx.x == 0) {
        float bs = 0.f;
        for (int i = 0; i < wpb; i++) bs += ssum[i];
        atomicAdd(&g_acc, (double)bs);
        __threadfence();
        unsigned int ticket = atomicAdd(&g_done, 1u);
        if (ticket == gridDim.x - 1) {
            double total = atomicAdd(&g_acc, 0.0);   // atomic read-back
            out[0] = (float)(total / (double)NTRIP);
        }
    }
}

extern "C" void kernel_launch(void* const* d_in, const int* in_sizes, int n_in,
                              void* d_out, int out_size) {
    // Resolve input ordering by element count (x: 4194304, trip: 600000)
    const float* x;
    const void*  trip;
    if (in_sizes[0] == NROWS * DIM) { x = (const float*)d_in[0]; trip = d_in[1]; }
    else                            { x = (const float*)d_in[1]; trip = d_in[0]; }

    float* out = (float*)d_out;

    prep_kernel<<<NROWS / 8, 256>>>(x);
    pack_kernel<<<(NTRIP + 255) / 256, 256>>>(trip);
    trip_kernel<<<GRID, 256>>>(out);
}

// round 14
// speedup vs baseline: 1.1202x; 1.1202x over previous
#include <cuda_runtime.h>
#include <math.h>

#define NROWS 8192
#define DIM   512
#define NTRIP 200000
#define GRID  888    // 6 blocks/SM x 148 SMs -> exactly one wave at ~40 regs

// Scratch (no allocations allowed in kernel_launch)
__device__ float        g_xn[NROWS];
__device__ float        g_sc[NROWS];                 // per-row dequant scale
__device__ double       g_acc;
__device__ int          g_is64;
__device__ unsigned int g_done;
__device__ int          g_xq[NROWS * DIM / 4];       // 4 MB int8 copy (packed s8x4)

// ---------------------------------------------------------------------------
// Kernel 1: fused prep — dtype detect + per-row norm/max + int8 quantize.
// ---------------------------------------------------------------------------
__global__ void prep_kernel(const float* __restrict__ x,
                            const unsigned int* __restrict__ tw) {
    if (blockIdx.x == 0 && threadIdx.x == 0) {
        int all_zero = 1;
        for (int i = 1; i < 96; i += 2) {
            if (tw[i] != 0u) { all_zero = 0; break; }
        }
        g_is64 = all_zero;
        g_acc  = 0.0;
        g_done = 0u;
    }

    int lane = threadIdx.x & 31;
    int row  = (blockIdx.x * blockDim.x + threadIdx.x) >> 5;
    if (row >= NROWS) return;

    const float4* rf = (const float4*)(x + (size_t)row * DIM);

    float4 v[4];
    float s = 0.f, m = 0.f;
#pragma unroll
    for (int k = 0; k < 4; k++) {
        v[k] = __ldg(&rf[lane + 32 * k]);
        s += v[k].x * v[k].x + v[k].y * v[k].y + v[k].z * v[k].z + v[k].w * v[k].w;
        m = fmaxf(m, fmaxf(fmaxf(fabsf(v[k].x), fabsf(v[k].y)),
                           fmaxf(fabsf(v[k].z), fabsf(v[k].w))));
    }
#pragma unroll
    for (int o = 16; o; o >>= 1) {
        s += __shfl_xor_sync(0xFFFFFFFFu, s, o);
        m = fmaxf(m, __shfl_xor_sync(0xFFFFFFFFu, m, o));
    }

    float scale = (m > 0.f) ? (m / 127.f) : 1.f;
    float inv   = (m > 0.f) ? (127.f / m) : 0.f;
    if (lane == 0) { g_xn[row] = s; g_sc[row] = scale; }

    int* qrow = g_xq + (size_t)row * (DIM / 4);
#pragma unroll
    for (int k = 0; k < 4; k++) {
        int qx = __float2int_rn(v[k].x * inv);
        int qy = __float2int_rn(v[k].y * inv);
        int qz = __float2int_rn(v[k].z * inv);
        int qw = __float2int_rn(v[k].w * inv);
        unsigned int packed = (unsigned int)(qx & 0xFF)
                            | ((unsigned int)(qy & 0xFF) << 8)
                            | ((unsigned int)(qz & 0xFF) << 16)
                            | ((unsigned int)(qw & 0xFF) << 24);
        qrow[lane + 32 * k] = (int)packed;   // coalesced STG.32
    }
}

// ---------------------------------------------------------------------------
// Kernel 2: 8-lane-group int8 gather + dp4a dots, 4 triplets/warp/iter.
// Front-batched 12 x LDG.128 per lane-group iteration (MLP=12), one wave.
// ---------------------------------------------------------------------------
__global__ void __launch_bounds__(256, 6) trip_kernel(
    const void* __restrict__ trip_raw,
    float* __restrict__ out)
{
    const int lane  = threadIdx.x & 31;
    const int grp   = lane >> 3;                  // 0..3: triplet group in warp
    const int sub   = lane & 7;                   // 0..7: lane within group
    const int wib   = threadIdx.x >> 5;
    const int wpb   = blockDim.x >> 5;
    const int gwarp = blockIdx.x * wpb + wib;
    const int nwarp = GRID * wpb;

    const int is64 = g_is64;
    const long long* t64 = (const long long*)trip_raw;
    const int*       t32 = (const int*)trip_raw;

    const uint4* xq = (const uint4*)g_xq;         // 32 uint4 per row
    float wsum = 0.f;                             // nonzero only on sub==0 lanes

    for (int base = gwarp * 4; base < NTRIP; base += nwarp * 4) {
        int t = base + grp;
        const int valid = (t < NTRIP);
        int tc = valid ? t : (NTRIP - 1);         // clamp to stay in bounds

        int a, p, n;
        if (is64) {
            a = (int)__ldg(&t64[3 * tc + 0]);
            p = (int)__ldg(&t64[3 * tc + 1]);
            n = (int)__ldg(&t64[3 * tc + 2]);
        } else {
            a = __ldg(&t32[3 * tc + 0]);
            p = __ldg(&t32[3 * tc + 1]);
            n = __ldg(&t32[3 * tc + 2]);
        }

        const uint4* ra = xq + (size_t)a * 32;
        const uint4* rp = xq + (size_t)p * 32;
        const uint4* rn = xq + (size_t)n * 32;

        // Front-batch all 12 gathers (each lane: 4 x 16B per row)
        uint4 qa[4], qp[4], qn[4];
#pragma unroll
        for (int c = 0; c < 4; c++) qa[c] = __ldg(&ra[sub + 8 * c]);
#pragma unroll
        for (int c = 0; c < 4; c++) qp[c] = __ldg(&rp[sub + 8 * c]);
#pragma unroll
        for (int c = 0; c < 4; c++) qn[c] = __ldg(&rn[sub + 8 * c]);

        int iap = 0, ian = 0;
#pragma unroll
        for (int c = 0; c < 4; c++) {
            iap = __dp4a((int)qa[c].x, (int)qp[c].x, iap);
            ian = __dp4a((int)qa[c].x, (int)qn[c].x, ian);
            iap = __dp4a((int)qa[c].y, (int)qp[c].y, iap);
            ian = __dp4a((int)qa[c].y, (int)qn[c].y, ian);
            iap = __dp4a((int)qa[c].z, (int)qp[c].z, iap);
            ian = __dp4a((int)qa[c].z, (int)qn[c].z, ian);
            iap = __dp4a((int)qa[c].w, (int)qp[c].w, iap);
            ian = __dp4a((int)qa[c].w, (int)qn[c].w, ian);
        }

        // 8-lane butterfly; one instruction serves all 4 groups
#pragma unroll
        for (int o = 4; o; o >>= 1) {
            iap += __shfl_xor_sync(0xFFFFFFFFu, iap, o);
            ian += __shfl_xor_sync(0xFFFFFFFFu, ian, o);
        }

        if (sub == 0 && valid) {
            float sa = g_sc[a];
            float dot_ap = sa * g_sc[p] * (float)iap;
            float dot_an = sa * g_sc[n] * (float)ian;
            float xna = g_xn[a];
            float dap = fmaxf(xna + g_xn[p] - 2.f * dot_ap, 0.f);
            float dan = fmaxf(xna + g_xn[n] - 2.f * dot_an, 0.f);
            float z = dap - dan;
            float sp = (z > 0.f) ? (z + log1pf(expf(-z))) : log1pf(expf(z));
            wsum += sp;
        }
    }

    // Combine the 4 group sums (lanes 0,8,16,24 hold values; others hold 0)
    wsum += __shfl_xor_sync(0xFFFFFFFFu, wsum, 8);
    wsum += __shfl_xor_sync(0xFFFFFFFFu, wsum, 16);

    __shared__ float ssum[8];
    if (lane == 0) ssum[wib] = wsum;
    __syncthreads();
    if (threadIdx.x == 0) {
        float bs = 0.f;
        for (int i = 0; i < wpb; i++) bs += ssum[i];
        atomicAdd(&g_acc, (double)bs);
        __threadfence();
        unsigned int ticket = atomicAdd(&g_done, 1u);
        if (ticket == gridDim.x - 1) {
            double total = atomicAdd(&g_acc, 0.0);   // atomic read-back
            out[0] = (float)(total / (double)NTRIP);
        }
    }
}

extern "C" void kernel_launch(void* const* d_in, const int* in_sizes, int n_in,
                              void* d_out, int out_size) {
    // Resolve input ordering by element count (x: 4194304, trip: 600000)
    const float* x;
    const void*  trip;
    if (in_sizes[0] == NROWS * DIM) { x = (const float*)d_in[0]; trip = d_in[1]; }
    else                            { x = (const float*)d_in[1]; trip = d_in[0]; }

    float* out = (float*)d_out;

    prep_kernel<<<NROWS / 8, 256>>>(x, (const unsigned int*)trip);
    trip_kernel<<<GRID, 256>>>(trip, out);
}